// round 3
// baseline (speedup 1.0000x reference)
#include <cuda_runtime.h>
#include <cuda_bf16.h>
#include <mma.h>
#include <math.h>

using namespace nvcuda;

#define D_DIM 128
#define V_DIM 100000
#define N_DIM 20000
#define E_DIM 640000
#define NODES_PER_BLK 64
#define NTILES ((N_DIM + NODES_PER_BLK - 1) / NODES_PER_BLK)   // 313
#define GBLK 157                                               // gemm grid; 2 tiles/block

// padded strides (conflict-free LDSM: row shift = 4 banks)
#define SA 264                 // bf16 elems per row for A / WM stage (528 B)
#define SC 132                 // float elems per row for C          (528 B)
#define WM_STAGE_BYTES (128 * SA * 2)                 // 67584
#define A_BYTES        (64  * SA * 2)                 // 33792 (== 64*SC*4)
#define DYN_SMEM_BYTES (WM_STAGE_BYTES + A_BYTES)     // 101376

// ---------------- scratch (device globals; no runtime allocation) ----------
__device__ int   g_rowptr[N_DIM + 1];
__device__ float g_xagg[(size_t)N_DIM * D_DIM];              // 10.24 MB
__device__ __nv_bfloat16 g_wm[D_DIM * 2 * D_DIM];            // [128][256] bf16
__device__ float g_partials[GBLK * D_DIM];

// ---------------- K1: rowptr from sorted segment_ids ----------------------
__global__ void rowptr_kernel(const int* __restrict__ seg) {
    int e = blockIdx.x * blockDim.x + threadIdx.x;
    if (e >= E_DIM) return;
    int s = seg[e];
    if (e == 0) {
        for (int t = 0; t <= s; ++t) g_rowptr[t] = 0;
    } else {
        int p = seg[e - 1];
        for (int t = p + 1; t <= s; ++t) g_rowptr[t] = e;
    }
    if (e == E_DIM - 1) {
        for (int t = s + 1; t <= N_DIM; ++t) g_rowptr[t] = E_DIM;
    }
}

// ---------------- K2: pack [W | M] as bf16 [128][256] ---------------------
__global__ void packwm_kernel(const float* __restrict__ W,
                              const float* __restrict__ M) {
    int i = blockIdx.x * blockDim.x + threadIdx.x;   // 0 .. 32767
    if (i >= D_DIM * 2 * D_DIM) return;
    int d = i >> 8;          // row (output channel)
    int k = i & 255;         // combined K
    float v = (k < D_DIM) ? W[d * D_DIM + k] : M[d * D_DIM + (k - D_DIM)];
    g_wm[i] = __float2bfloat16(v);
}

// ---------------- K3: gather + segment-sum (one block per node) -----------
__global__ void agg_kernel(const int* __restrict__ nbr,
                           const float* __restrict__ emb) {
    int n = blockIdx.x;
    int start = g_rowptr[n];
    int end   = g_rowptr[n + 1];
    int lane = threadIdx.x & 31;
    int w    = threadIdx.x >> 5;

    float4 acc = make_float4(0.f, 0.f, 0.f, 0.f);
    int e = start + w;
    // unroll-by-2: two independent gathers in flight per iteration
    for (; e + 4 < end; e += 8) {
        int r1 = __ldg(&nbr[e]);
        int r2 = __ldg(&nbr[e + 4]);
        float4 v1 = __ldg(((const float4*)(emb + (size_t)r1 * D_DIM)) + lane);
        float4 v2 = __ldg(((const float4*)(emb + (size_t)r2 * D_DIM)) + lane);
        acc.x += v1.x + v2.x; acc.y += v1.y + v2.y;
        acc.z += v1.z + v2.z; acc.w += v1.w + v2.w;
    }
    if (e < end) {
        int r = __ldg(&nbr[e]);
        float4 v = __ldg(((const float4*)(emb + (size_t)r * D_DIM)) + lane);
        acc.x += v.x; acc.y += v.y; acc.z += v.z; acc.w += v.w;
    }
    __shared__ float4 sbuf[4][32];
    sbuf[w][lane] = acc;
    __syncthreads();
    if (w == 0) {
        float4 a = sbuf[0][lane], b = sbuf[1][lane];
        float4 c = sbuf[2][lane], d = sbuf[3][lane];
        float4 o = make_float4(a.x + b.x + c.x + d.x,
                               a.y + b.y + c.y + d.y,
                               a.z + b.z + c.z + d.z,
                               a.w + b.w + c.w + d.w);
        ((float4*)(g_xagg + (size_t)n * D_DIM))[lane] = o;
    }
}

// ---------------- K4: relu(X @ [W|M]^T) + row-reduce via wmma bf16 --------
// Grid 157 x 256 threads; each block stages WM once, loops over 2 tiles of
// 64 nodes. A-build: thread t = (row r = t>>2, quarter q = t&3), 8 unrolled
// independent float4 gathers per source (MLP=8). Column sums accumulate in
// registers across tiles; one partials write per block.
__global__ __launch_bounds__(256, 2)
void gemm_kernel(const int* __restrict__ node_ids,
                 const float* __restrict__ emb) {
    extern __shared__ unsigned char dynsmem[];
    __nv_bfloat16* WMs = (__nv_bfloat16*)dynsmem;                    // [128][SA]
    __nv_bfloat16* As  = (__nv_bfloat16*)(dynsmem + WM_STAGE_BYTES); // [64][SA]
    float*         Cs  = (float*)(dynsmem + WM_STAGE_BYTES);         // [64][SC]

    __shared__ float red[256];

    const int tid = threadIdx.x;
    const int w   = tid >> 5;

    // stage WM once (padded rows: 32 real uint4, stride 33 uint4)
    {
        const uint4* src = (const uint4*)g_wm;
        uint4* dst = (uint4*)WMs;
        #pragma unroll
        for (int i = tid; i < 4096; i += 256) {
            int r = i >> 5, c = i & 31;
            dst[r * 33 + c] = src[i];
        }
    }

    const int r = tid >> 2;      // A row this thread fills (0..63)
    const int q = tid & 3;       // quarter of the row
    float acc_partial = 0.0f;    // per (tid<128) column running sum

    for (int t = blockIdx.x; t < NTILES; t += GBLK) {
        const int n0 = t * NODES_PER_BLK;
        const int n  = n0 + r;
        const bool valid = (n < N_DIM);

        __syncthreads();   // previous tile's Cs fully consumed before overlay

        // ---- build A (batched, independent loads) ----
        {
            const float4 z = make_float4(0.f, 0.f, 0.f, 0.f);
            int nid = valid ? __ldg(&node_ids[n]) : 0;
            const float4* esrc = (const float4*)(emb    + (size_t)nid * D_DIM) + q * 8;
            const float4* xsrc = (const float4*)(g_xagg + (size_t)n   * D_DIM) + q * 8;

            float4 v[8];
            #pragma unroll
            for (int j = 0; j < 8; ++j) v[j] = valid ? __ldg(esrc + j) : z;
            #pragma unroll
            for (int j = 0; j < 8; ++j) {
                __nv_bfloat162* dst = (__nv_bfloat162*)(As + r * SA + (q * 8 + j) * 4);
                dst[0] = __float22bfloat162_rn(make_float2(v[j].x, v[j].y));
                dst[1] = __float22bfloat162_rn(make_float2(v[j].z, v[j].w));
            }
            #pragma unroll
            for (int j = 0; j < 8; ++j) v[j] = valid ? __ldg(xsrc + j) : z;
            #pragma unroll
            for (int j = 0; j < 8; ++j) {
                __nv_bfloat162* dst = (__nv_bfloat162*)(As + r * SA + D_DIM + (q * 8 + j) * 4);
                dst[0] = __float22bfloat162_rn(make_float2(v[j].x, v[j].y));
                dst[1] = __float22bfloat162_rn(make_float2(v[j].z, v[j].w));
            }
        }
        __syncthreads();

        // ---- MMA: warp w owns output cols [16w,16w+16), all 64 rows ----
        wmma::fragment<wmma::accumulator, 16, 16, 16, float> cf[4];
        #pragma unroll
        for (int b = 0; b < 4; ++b) wmma::fill_fragment(cf[b], 0.0f);

        #pragma unroll
        for (int kk = 0; kk < 16; ++kk) {
            wmma::fragment<wmma::matrix_b, 16, 16, 16, __nv_bfloat16, wmma::col_major> bf;
            wmma::load_matrix_sync(bf, WMs + (w * 16) * SA + kk * 16, SA);
            #pragma unroll
            for (int b = 0; b < 4; ++b) {
                wmma::fragment<wmma::matrix_a, 16, 16, 16, __nv_bfloat16, wmma::row_major> af;
                wmma::load_matrix_sync(af, As + (b * 16) * SA + kk * 16, SA);
                wmma::mma_sync(cf[b], af, bf, cf[b]);
            }
        }
        __syncthreads();   // all warps done reading A before overlay with C

        #pragma unroll
        for (int b = 0; b < 4; ++b) {
            #pragma unroll
            for (int e2 = 0; e2 < cf[b].num_elements; ++e2)
                cf[b].x[e2] = fmaxf(cf[b].x[e2], 0.0f);
            wmma::store_matrix_sync(Cs + (b * 16) * SC + w * 16, cf[b], SC,
                                    wmma::mem_row_major);
        }
        __syncthreads();

        // ---- column-sum the 64x128 relu'd tile ----
        {
            int col  = tid & 127;
            int part = tid >> 7;            // 0/1 -> rows [0,32) / [32,64)
            float s = 0.f;
            #pragma unroll
            for (int rr = part * 32; rr < part * 32 + 32; ++rr)
                s += Cs[rr * SC + col];
            red[tid] = s;
        }
        __syncthreads();
        if (tid < 128) acc_partial += red[tid] + red[tid + 128];
    }

    if (tid < 128)
        g_partials[blockIdx.x * D_DIM + tid] = acc_partial;
}

// ---------------- K5: reduce partials + softmax ----------------------------
__global__ void final_kernel(float* __restrict__ out) {
    const int tid = threadIdx.x;          // 512 threads
    const int col = tid & 127;
    const int q   = tid >> 7;             // quarter
    float acc = 0.f;
    for (int b = q; b < GBLK; b += 4)
        acc += g_partials[b * D_DIM + col];

    __shared__ float buf[512];
    buf[tid] = acc;
    __syncthreads();
    float logit = 0.f;
    if (tid < 128)
        logit = buf[tid] + buf[tid + 128] + buf[tid + 256] + buf[tid + 384];
    __syncthreads();

    buf[tid] = (tid < 128) ? logit : -INFINITY;
    __syncthreads();
    for (int st = 256; st > 0; st >>= 1) {
        if (tid < st) buf[tid] = fmaxf(buf[tid], buf[tid + st]);
        __syncthreads();
    }
    float mx = buf[0];
    __syncthreads();

    float e = (tid < 128) ? expf(logit - mx) : 0.f;
    buf[tid] = e;
    __syncthreads();
    for (int st = 256; st > 0; st >>= 1) {
        if (tid < st) buf[tid] += buf[tid + st];
        __syncthreads();
    }
    if (tid < 128) out[tid] = e / buf[0];
}

// ---------------- launcher --------------------------------------------------
extern "C" void kernel_launch(void* const* d_in, const int* in_sizes, int n_in,
                              void* d_out, int out_size) {
    const int*   node_ids     = (const int*)d_in[0];
    const int*   neighbor_ids = (const int*)d_in[1];
    const int*   segment_ids  = (const int*)d_in[2];
    const float* W            = (const float*)d_in[3];
    const float* M            = (const float*)d_in[4];
    const float* emb          = (const float*)d_in[5];
    float*       out          = (float*)d_out;

    cudaFuncSetAttribute(gemm_kernel,
                         cudaFuncAttributeMaxDynamicSharedMemorySize,
                         DYN_SMEM_BYTES);

    rowptr_kernel<<<(E_DIM + 255) / 256, 256>>>(segment_ids);
    packwm_kernel<<<(D_DIM * 2 * D_DIM + 255) / 256, 256>>>(W, M);
    agg_kernel<<<N_DIM, 128>>>(neighbor_ids, emb);
    gemm_kernel<<<GBLK, 256, DYN_SMEM_BYTES>>>(node_ids, emb);
    final_kernel<<<1, 512>>>(out);
}

// round 4
// speedup vs baseline: 1.1120x; 1.1120x over previous
#include <cuda_runtime.h>
#include <cuda_bf16.h>
#include <mma.h>
#include <math.h>

using namespace nvcuda;

#define D_DIM 128
#define V_DIM 100000
#define N_DIM 20000
#define E_DIM 640000
#define NODES_PER_BLK 64
#define NTILES ((N_DIM + NODES_PER_BLK - 1) / NODES_PER_BLK)   // 313

// padded strides (conflict-free LDSM: 528B row shift = 4 banks)
#define SA 264                 // bf16 elems per A row (528 B)
#define SC 132                 // float elems per C row (528 B)
#define A_BYTES (64 * SA * 2)  // 33792 (== 64*SC*4, C overlays A)

// ---------------- scratch (device globals; no runtime allocation) ----------
__device__ int   g_rowptr[N_DIM + 1];
__device__ __nv_bfloat16 g_wm[D_DIM * 2 * D_DIM];            // [128][256] bf16
__device__ float g_partials[NTILES * D_DIM];

// ---------------- K1: rowptr from sorted segment_ids ----------------------
__global__ void rowptr_kernel(const int* __restrict__ seg) {
    int e = blockIdx.x * blockDim.x + threadIdx.x;
    if (e >= E_DIM) return;
    int s = seg[e];
    if (e == 0) {
        for (int t = 0; t <= s; ++t) g_rowptr[t] = 0;
    } else {
        int p = seg[e - 1];
        for (int t = p + 1; t <= s; ++t) g_rowptr[t] = e;
    }
    if (e == E_DIM - 1) {
        for (int t = s + 1; t <= N_DIM; ++t) g_rowptr[t] = E_DIM;
    }
}

// ---------------- K2: pack [W | M] as bf16 [128][256] ---------------------
__global__ void packwm_kernel(const float* __restrict__ W,
                              const float* __restrict__ M) {
    int i = blockIdx.x * blockDim.x + threadIdx.x;   // 0 .. 32767
    if (i >= D_DIM * 2 * D_DIM) return;
    int d = i >> 8;          // row (output channel)
    int k = i & 255;         // combined K
    float v = (k < D_DIM) ? W[d * D_DIM + k] : M[d * D_DIM + (k - D_DIM)];
    g_wm[i] = __float2bfloat16(v);
}

// ---------------- helpers ---------------------------------------------------
__device__ __forceinline__ uint2 pack_bf16x4(float4 v) {
    __nv_bfloat162 lo = __float22bfloat162_rn(make_float2(v.x, v.y));
    __nv_bfloat162 hi = __float22bfloat162_rn(make_float2(v.z, v.w));
    uint2 u;
    u.x = *(unsigned int*)&lo;
    u.y = *(unsigned int*)&hi;
    return u;
}

// ---------------- K3: FUSED gather + segment-sum + GEMM + relu + colsum ----
// One block per 64-node tile, 512 threads = 16 warps.
// Phase 1 (gather): warp w owns rows [4w, 4w+4). For each node: lane = float4
//   column; self emb row -> A[:,0:128); edge-aggregated emb -> A[:,128:256).
//   Edge loop unrolled x4 (independent gathers, MLP~4-5).
// Phase 2 (MMA): warp w: row-band rb=w>>3 (32 rows, 2 frags), col-band cb=w&7
//   (16 cols). B fragments loaded per-kk from global g_wm (L1-hot).
// Phase 3: relu -> C (overlays A) -> column-sum -> per-block partials.
__global__ __launch_bounds__(512)
void fused_kernel(const int* __restrict__ node_ids,
                  const int* __restrict__ nbr,
                  const float* __restrict__ emb) {
    extern __shared__ unsigned char dynsmem[];
    __nv_bfloat16* As = (__nv_bfloat16*)dynsmem;   // [64][SA]
    float*         Cs = (float*)dynsmem;           // [64][SC] (overlay)
    __shared__ float red[512];

    const int tid  = threadIdx.x;
    const int w    = tid >> 5;
    const int lane = tid & 31;
    const int n0   = blockIdx.x * NODES_PER_BLK;

    // ---------- Phase 1: gather + aggregate into A ----------
    #pragma unroll
    for (int i = 0; i < 4; ++i) {
        const int r = w * 4 + i;          // row within tile
        const int n = n0 + r;
        float4 self = make_float4(0.f, 0.f, 0.f, 0.f);
        float4 acc  = make_float4(0.f, 0.f, 0.f, 0.f);

        if (n < N_DIM) {
            int nid = __ldg(&node_ids[n]);
            self = __ldg(((const float4*)(emb + (size_t)nid * D_DIM)) + lane);

            int s = g_rowptr[n];
            int e = g_rowptr[n + 1];
            int j = s;
            for (; j + 3 < e; j += 4) {
                int i0 = __ldg(&nbr[j + 0]);
                int i1 = __ldg(&nbr[j + 1]);
                int i2 = __ldg(&nbr[j + 2]);
                int i3 = __ldg(&nbr[j + 3]);
                float4 v0 = __ldg(((const float4*)(emb + (size_t)i0 * D_DIM)) + lane);
                float4 v1 = __ldg(((const float4*)(emb + (size_t)i1 * D_DIM)) + lane);
                float4 v2 = __ldg(((const float4*)(emb + (size_t)i2 * D_DIM)) + lane);
                float4 v3 = __ldg(((const float4*)(emb + (size_t)i3 * D_DIM)) + lane);
                acc.x += (v0.x + v1.x) + (v2.x + v3.x);
                acc.y += (v0.y + v1.y) + (v2.y + v3.y);
                acc.z += (v0.z + v1.z) + (v2.z + v3.z);
                acc.w += (v0.w + v1.w) + (v2.w + v3.w);
            }
            for (; j < e; ++j) {
                int ix = __ldg(&nbr[j]);
                float4 v = __ldg(((const float4*)(emb + (size_t)ix * D_DIM)) + lane);
                acc.x += v.x; acc.y += v.y; acc.z += v.z; acc.w += v.w;
            }
        }
        *(uint2*)(As + r * SA +          lane * 4) = pack_bf16x4(self);
        *(uint2*)(As + r * SA + D_DIM +  lane * 4) = pack_bf16x4(acc);
    }
    __syncthreads();

    // ---------- Phase 2: MMA ----------
    const int rb = w >> 3;    // 0/1 -> rows [32rb, 32rb+32)
    const int cb = w & 7;     // cols [16cb, 16cb+16)

    wmma::fragment<wmma::accumulator, 16, 16, 16, float> c0, c1;
    wmma::fill_fragment(c0, 0.0f);
    wmma::fill_fragment(c1, 0.0f);

    #pragma unroll
    for (int kk = 0; kk < 16; ++kk) {
        wmma::fragment<wmma::matrix_b, 16, 16, 16, __nv_bfloat16, wmma::col_major> bf;
        wmma::load_matrix_sync(bf, g_wm + (cb * 16) * 256 + kk * 16, 256);
        wmma::fragment<wmma::matrix_a, 16, 16, 16, __nv_bfloat16, wmma::row_major> a0, a1;
        wmma::load_matrix_sync(a0, As + (rb * 32) * SA + kk * 16, SA);
        wmma::load_matrix_sync(a1, As + (rb * 32 + 16) * SA + kk * 16, SA);
        wmma::mma_sync(c0, a0, bf, c0);
        wmma::mma_sync(c1, a1, bf, c1);
    }
    __syncthreads();    // all warps done reading A before C overlay

    #pragma unroll
    for (int t = 0; t < c0.num_elements; ++t) {
        c0.x[t] = fmaxf(c0.x[t], 0.0f);
        c1.x[t] = fmaxf(c1.x[t], 0.0f);
    }
    wmma::store_matrix_sync(Cs + (rb * 32) * SC + cb * 16, c0, SC, wmma::mem_row_major);
    wmma::store_matrix_sync(Cs + (rb * 32 + 16) * SC + cb * 16, c1, SC, wmma::mem_row_major);
    __syncthreads();

    // ---------- Phase 3: column-sum 64x128 -> partials ----------
    {
        const int col  = tid & 127;
        const int part = tid >> 7;        // 0..3 -> 16-row bands
        float s = 0.f;
        #pragma unroll
        for (int rr = part * 16; rr < part * 16 + 16; ++rr)
            s += Cs[rr * SC + col];
        red[tid] = s;
    }
    __syncthreads();
    if (tid < 128)
        g_partials[blockIdx.x * D_DIM + tid] =
            red[tid] + red[tid + 128] + red[tid + 256] + red[tid + 384];
}

// ---------------- K4: reduce partials + softmax ----------------------------
__global__ void final_kernel(float* __restrict__ out) {
    const int tid = threadIdx.x;          // 512 threads
    const int col = tid & 127;
    const int q   = tid >> 7;             // quarter
    float acc = 0.f;
    for (int b = q; b < NTILES; b += 4)
        acc += g_partials[b * D_DIM + col];

    __shared__ float buf[512];
    buf[tid] = acc;
    __syncthreads();
    float logit = 0.f;
    if (tid < 128)
        logit = buf[tid] + buf[tid + 128] + buf[tid + 256] + buf[tid + 384];
    __syncthreads();

    buf[tid] = (tid < 128) ? logit : -INFINITY;
    __syncthreads();
    for (int st = 256; st > 0; st >>= 1) {
        if (tid < st) buf[tid] = fmaxf(buf[tid], buf[tid + st]);
        __syncthreads();
    }
    float mx = buf[0];
    __syncthreads();

    float e = (tid < 128) ? expf(logit - mx) : 0.f;
    buf[tid] = e;
    __syncthreads();
    for (int st = 256; st > 0; st >>= 1) {
        if (tid < st) buf[tid] += buf[tid + st];
        __syncthreads();
    }
    if (tid < 128) out[tid] = e / buf[0];
}

// ---------------- launcher --------------------------------------------------
extern "C" void kernel_launch(void* const* d_in, const int* in_sizes, int n_in,
                              void* d_out, int out_size) {
    const int*   node_ids     = (const int*)d_in[0];
    const int*   neighbor_ids = (const int*)d_in[1];
    const int*   segment_ids  = (const int*)d_in[2];
    const float* W            = (const float*)d_in[3];
    const float* M            = (const float*)d_in[4];
    const float* emb          = (const float*)d_in[5];
    float*       out          = (float*)d_out;

    rowptr_kernel<<<(E_DIM + 255) / 256, 256>>>(segment_ids);
    packwm_kernel<<<(D_DIM * 2 * D_DIM + 255) / 256, 256>>>(W, M);
    fused_kernel<<<NTILES, 512, A_BYTES>>>(node_ids, neighbor_ids, emb);
    final_kernel<<<1, 512>>>(out);
}